// round 17
// baseline (speedup 1.0000x reference)
#include <cuda_runtime.h>
#include <cuda_fp16.h>
#include <cstdint>

#define BB   2
#define TT   2048
#define HH   16
#define DH   64
#define DD   1024
#define BH   (BB*HH)
#define TILE 128
#define NT   (TT/TILE)
#define NCHUNK 72      // sum over i of ceil((NT-i)/2)

// fp16 scratch (8 MB each, 24 MB total -> L2 resident)
__device__ __half g_Vh [(size_t)BH * TT * DH];
__device__ __half g_Vl [(size_t)BH * TT * DH];
__device__ __half g_Svh[(size_t)BH * TT * DH];

__device__ __forceinline__ uint32_t smem_u32(const void* p) {
    uint32_t a;
    asm("{ .reg .u64 t; cvta.to.shared.u64 t, %1; cvt.u32.u64 %0, t; }"
        : "=r"(a) : "l"(p));
    return a;
}

#define LDSM4(r, addr) \
    asm volatile("ldmatrix.sync.aligned.m8n8.x4.shared.b16 {%0,%1,%2,%3}, [%4];" \
        : "=r"((r)[0]), "=r"((r)[1]), "=r"((r)[2]), "=r"((r)[3]) : "r"(addr))

#define MMA16816(d, a, b0, b1) \
    asm volatile("mma.sync.aligned.m16n8k16.row.col.f32.f16.f16.f32 " \
        "{%0,%1,%2,%3},{%4,%5,%6,%7},{%8,%9},{%0,%1,%2,%3};" \
        : "+f"((d)[0]), "+f"((d)[1]), "+f"((d)[2]), "+f"((d)[3]) \
        : "r"((a)[0]), "r"((a)[1]), "r"((a)[2]), "r"((a)[3]), "r"(b0), "r"(b1))

#define CP_ASYNC16(dst, src) \
    asm volatile("cp.async.cg.shared.global [%0], [%1], 16;" \
        :: "r"(dst), "l"(src) : "memory")
#define CP_COMMIT() asm volatile("cp.async.commit_group;" ::: "memory")
#define CP_WAIT0()  asm volatile("cp.async.wait_group 0;" ::: "memory")
#define CP_WAIT1()  asm volatile("cp.async.wait_group 1;" ::: "memory")

#define LDBH 144   // bytes per smem fp16 tile row (64 halfs + 16B pad)

// ============================================================================
// Kernel 1 (round-16 form, UNCHANGED): normalize rows -> Vh/Vl,
// Sv = V*S via mma.sync, Svh = fp16(Sv). grid (BH, NT*2), 128 threads.
// ============================================================================
#define Q_BSH 0
#define Q_BSL 9216
#define Q_VH  18432
#define Q_VL  27648
#define Q_AS  36864
#define SMEM_PREP 53504

__global__ __launch_bounds__(128) void prep_kernel(const float* __restrict__ x,
                                                   const float* __restrict__ A) {
    extern __shared__ char sp[];
    const uint32_t sb = smem_u32(sp);
    float* As = (float*)(sp + Q_AS);
    const int tid  = threadIdx.x;
    const int warp = tid >> 5;
    const int lane = tid & 31;
    const int bh = blockIdx.x;
    const int b  = bh / HH;
    const int h  = bh % HH;
    const int t0c = blockIdx.y * 64;

    float2 v[16];
    {
        const float* xbase = x + ((size_t)(b * TT + t0c + warp * 16)) * DD + h * DH + 2 * lane;
        #pragma unroll
        for (int r = 0; r < 16; ++r)
            v[r] = *(const float2*)(xbase + (size_t)r * DD);
    }

    {
        const float4* Ah4 = (const float4*)(A + (size_t)h * DH * DH);
        #pragma unroll
        for (int p = 0; p < 8; ++p) {
            const int f  = p * 128 + tid;
            const int d  = f >> 4;
            const int c4 = (f & 15) * 4;
            const float4 a = Ah4[f];
            As[d * 65 + c4 + 0] = a.x;
            As[d * 65 + c4 + 1] = a.y;
            As[d * 65 + c4 + 2] = a.z;
            As[d * 65 + c4 + 3] = a.w;
        }
    }
    __syncthreads();

    #pragma unroll
    for (int p = 0; p < 32; ++p) {
        const int idx = p * 128 + tid;
        const int e = idx >> 6, d = idx & 63;
        const float s = As[d * 65 + e] - As[e * 65 + d];
        const __half hi = __float2half_rn(s);
        const __half lo = __float2half_rn(s - __half2float(hi));
        *(__half*)(sp + Q_BSH + e * LDBH + d * 2) = hi;
        *(__half*)(sp + Q_BSL + e * LDBH + d * 2) = lo;
    }

    #pragma unroll
    for (int r = 0; r < 16; ++r) {
        float ss = v[r].x * v[r].x + v[r].y * v[r].y;
        #pragma unroll
        for (int o = 16; o; o >>= 1) ss += __shfl_xor_sync(0xffffffffu, ss, o);
        const float sc = 1.0f / fmaxf(sqrtf(ss), 1e-12f);
        v[r].x *= sc; v[r].y *= sc;
        const __half hx = __float2half_rn(v[r].x);
        const __half hy = __float2half_rn(v[r].y);
        const __half2 H(hx, hy);
        const __half2 L = __floats2half2_rn(v[r].x - __half2float(hx),
                                            v[r].y - __half2float(hy));
        const int lr   = warp * 16 + r;
        const size_t gofs = ((size_t)bh * TT + t0c + lr) * DH + 2 * lane;
        *(__half2*)&g_Vh[gofs] = H;
        *(__half2*)&g_Vl[gofs] = L;
        *(__half2*)(sp + Q_VH + lr * LDBH + lane * 4) = H;
        *(__half2*)(sp + Q_VL + lr * LDBH + lane * 4) = L;
    }
    __syncthreads();

    const uint32_t aB = sb + Q_VH + (uint32_t)(warp * 16 + (lane & 15)) * LDBH
                      + ((uint32_t)(lane >> 4)) * 16;
    const uint32_t bB = sb + Q_BSH + (uint32_t)((lane & 7) | ((lane >> 1) & 8)) * LDBH
                      + ((uint32_t)(lane & 8)) * 2;

    float acc[8][4];
    #pragma unroll
    for (int q = 0; q < 8; ++q)
        #pragma unroll
        for (int c = 0; c < 4; ++c) acc[q][c] = 0.f;

    #pragma unroll
    for (int kk = 0; kk < 4; ++kk) {
        uint32_t ah[4];
        LDSM4(ah, aB + kk * 32);
        #pragma unroll
        for (int n16 = 0; n16 < 4; ++n16) {
            uint32_t bhf[4], blf[4];
            LDSM4(bhf, bB + n16 * 16 * LDBH + kk * 32);
            LDSM4(blf, bB + (Q_BSL - Q_BSH) + n16 * 16 * LDBH + kk * 32);
            MMA16816(acc[2 * n16],     ah, bhf[0], bhf[1]);
            MMA16816(acc[2 * n16 + 1], ah, bhf[2], bhf[3]);
            MMA16816(acc[2 * n16],     ah, blf[0], blf[1]);
            MMA16816(acc[2 * n16 + 1], ah, blf[2], blf[3]);
        }
    }

    const int r = warp * 16 + (lane >> 2);
    #pragma unroll
    for (int q = 0; q < 8; ++q) {
        const int col = q * 8 + (lane & 3) * 2;
        const __half2 h0 = __floats2half2_rn(acc[q][0], acc[q][1]);
        const __half2 h1 = __floats2half2_rn(acc[q][2], acc[q][3]);
        *(__half2*)&g_Svh[((size_t)bh * TT + t0c + r) * DH + col]     = h0;
        *(__half2*)&g_Svh[((size_t)bh * TT + t0c + r + 8) * DH + col] = h1;
    }
}

// ============================================================================
// Kernel 2: fp16 mma wedge, TWO j-tiles per CTA with B2 prefetch.
// A tile loaded once; stage aliases dead B1 region. grid (NCHUNK, BH), 256 thr.
// ============================================================================
#define T_A    0
#define T_B1h  18432
#define T_B1l  36864
#define T_B2h  55296
#define T_B2l  73728
#define P_STG  18432            // stage aliases B1h+B1l after mma1
#define WSLICE 4608
#define SMEM_WEDGE 92160

__device__ __forceinline__ void cp_tile(uint32_t dst, const __half* __restrict__ src,
                                        int tid) {
    #pragma unroll
    for (int p = 0; p < 4; ++p) {
        const int f   = p * 256 + tid;
        const int row = f >> 3;
        const int c   = f & 7;
        CP_ASYNC16(dst + row * LDBH + c * 16, (const char*)src + f * 16);
    }
}

struct WAcc { float a[4][4][4]; };

__device__ __forceinline__ void run_mma(uint32_t sb, uint32_t bhOff, uint32_t blOff,
                                        int wm, int wn, int lane, WAcc& W) {
    const uint32_t aB = sb + T_A + (uint32_t)(wm * 64 + (lane & 15)) * LDBH
                      + ((uint32_t)(lane >> 4)) * 16;
    const uint32_t bn = (uint32_t)((lane & 7) | ((lane >> 1) & 8));
    const uint32_t bB = sb + bhOff + ((uint32_t)(wn * 32) + bn) * LDBH
                      + ((uint32_t)(lane & 8)) * 2;
    const uint32_t dlo = blOff - bhOff;

    #pragma unroll
    for (int mt = 0; mt < 4; ++mt)
        #pragma unroll
        for (int nt = 0; nt < 4; ++nt)
            #pragma unroll
            for (int q = 0; q < 4; ++q) W.a[mt][nt][q] = 0.f;

    #pragma unroll
    for (int kk = 0; kk < 4; ++kk) {
        uint32_t bh0[4], bh1[4], bl0[4], bl1[4];
        LDSM4(bh0, bB + kk * 32);
        LDSM4(bh1, bB + 16 * LDBH + kk * 32);
        LDSM4(bl0, bB + dlo + kk * 32);
        LDSM4(bl1, bB + dlo + 16 * LDBH + kk * 32);
        #pragma unroll
        for (int mt = 0; mt < 4; ++mt) {
            uint32_t ah[4];
            LDSM4(ah, aB + mt * 16 * LDBH + kk * 32);
            MMA16816(W.a[mt][0], ah, bh0[0], bh0[1]);
            MMA16816(W.a[mt][1], ah, bh0[2], bh0[3]);
            MMA16816(W.a[mt][2], ah, bh1[0], bh1[1]);
            MMA16816(W.a[mt][3], ah, bh1[2], bh1[3]);
            MMA16816(W.a[mt][0], ah, bl0[0], bl0[1]);
            MMA16816(W.a[mt][1], ah, bl0[2], bl0[3]);
            MMA16816(W.a[mt][2], ah, bl1[0], bl1[1]);
            MMA16816(W.a[mt][3], ah, bl1[2], bl1[3]);
        }
    }
}

__device__ __forceinline__ void run_epi(char* sm, float* __restrict__ outb,
                                        int i0, int j0, int wm, int wn,
                                        int w, int lane, const WAcc& W) {
    float* stg = (float*)(sm + P_STG + w * WSLICE);
    const int rql = lane >> 2;
    const int cql = (lane & 3) * 2;

    #pragma unroll
    for (int mt = 0; mt < 4; ++mt) {
        #pragma unroll
        for (int nt = 0; nt < 4; ++nt) {
            const int col = nt * 8 + cql;
            *(float2*)&stg[rql * 40 + col]       = make_float2(W.a[mt][nt][0], W.a[mt][nt][1]);
            *(float2*)&stg[(rql + 8) * 40 + col] = make_float2(W.a[mt][nt][2], W.a[mt][nt][3]);
        }
        __syncwarp();
        #pragma unroll
        for (int pp = 0; pp < 4; ++pp) {
            const int r = pp * 4 + (lane >> 3);
            const float4 vv = *(const float4*)&stg[r * 40 + (lane & 7) * 4];
            const int grow = i0 + wm * 64 + mt * 16 + r;
            __stcs((float4*)&outb[(size_t)grow * TT + j0 + wn * 32 + (lane & 7) * 4], vv);
        }
        __syncwarp();
    }

    if (i0 != j0) {
        #pragma unroll
        for (int cc = 0; cc < 2; ++cc) {
            #pragma unroll
            for (int ntl = 0; ntl < 2; ++ntl) {
                const int nt = cc * 2 + ntl;
                const int c0 = ntl * 8 + cql;
                #pragma unroll
                for (int mt = 0; mt < 4; ++mt) {
                    const int rbase = mt * 16 + rql;
                    stg[c0 * 72 + rbase]           = -W.a[mt][nt][0];
                    stg[(c0 + 1) * 72 + rbase]     = -W.a[mt][nt][1];
                    stg[c0 * 72 + rbase + 8]       = -W.a[mt][nt][2];
                    stg[(c0 + 1) * 72 + rbase + 8] = -W.a[mt][nt][3];
                }
            }
            __syncwarp();
            #pragma unroll
            for (int pp = 0; pp < 8; ++pp) {
                const int c = pp * 2 + (lane >> 4);
                const float4 vv = *(const float4*)&stg[c * 72 + (lane & 15) * 4];
                const int grow = j0 + wn * 32 + cc * 16 + c;
                __stcs((float4*)&outb[(size_t)grow * TT + i0 + wm * 64 + (lane & 15) * 4], vv);
            }
            __syncwarp();
        }
    }
}

__global__ __launch_bounds__(256, 2) void wedge_mma(float* __restrict__ out) {
    extern __shared__ char sm[];
    const uint32_t sb = smem_u32(sm);
    const int tid  = threadIdx.x;
    const int w    = tid >> 5;
    const int lane = tid & 31;
    const int bh   = blockIdx.y;
    const int wm   = w >> 2;
    const int wn   = w & 3;

    // decode chunk -> (i, j1, j2)
    int c = blockIdx.x;
    int i = 0;
    while (c >= (NT - i + 1) / 2) { c -= (NT - i + 1) / 2; ++i; }
    const int j1 = i + 2 * c;
    const int j2 = (j1 + 1 <= NT - 1) ? j1 + 1 : -1;

    const __half* Svb = g_Svh + (size_t)bh * TT * DH;
    const __half* Vhb = g_Vh  + (size_t)bh * TT * DH;
    const __half* Vlb = g_Vl  + (size_t)bh * TT * DH;
    float* outb = out + (size_t)bh * TT * TT;

    // prefetch: group1 = A + B1; group2 = B2 (possibly empty)
    cp_tile(sb + T_A,   Svb + (size_t)i  * TILE * DH, tid);
    cp_tile(sb + T_B1h, Vhb + (size_t)j1 * TILE * DH, tid);
    cp_tile(sb + T_B1l, Vlb + (size_t)j1 * TILE * DH, tid);
    CP_COMMIT();
    if (j2 >= 0) {
        cp_tile(sb + T_B2h, Vhb + (size_t)j2 * TILE * DH, tid);
        cp_tile(sb + T_B2l, Vlb + (size_t)j2 * TILE * DH, tid);
    }
    CP_COMMIT();

    CP_WAIT1();            // A + B1 ready (this thread)
    __syncthreads();       // visible CTA-wide

    WAcc W;
    run_mma(sb, T_B1h, T_B1l, wm, wn, lane, W);

    CP_WAIT0();            // B2 ready (this thread)
    __syncthreads();       // B1 dead (stage alias safe) + B2 visible CTA-wide

    run_epi(sm, outb, i * TILE, j1 * TILE, wm, wn, w, lane, W);

    if (j2 >= 0) {
        // A and B2 untouched by epi (stage confined to B1 region); per-warp
        // program order guarantees this warp's epi1 stage use is complete.
        run_mma(sb, T_B2h, T_B2l, wm, wn, lane, W);
        run_epi(sm, outb, i * TILE, j2 * TILE, wm, wn, w, lane, W);
    }
}

// ============================================================================
extern "C" void kernel_launch(void* const* d_in, const int* in_sizes, int n_in,
                              void* d_out, int out_size) {
    (void)in_sizes; (void)n_in; (void)out_size;
    const float* x = (const float*)d_in[0];
    const float* A = (const float*)d_in[1];
    float* out = (float*)d_out;

    cudaFuncSetAttribute(prep_kernel, cudaFuncAttributeMaxDynamicSharedMemorySize, SMEM_PREP);
    prep_kernel<<<dim3(BH, NT * 2), 128, SMEM_PREP>>>(x, A);

    cudaFuncSetAttribute(wedge_mma, cudaFuncAttributeMaxDynamicSharedMemorySize, SMEM_WEDGE);
    wedge_mma<<<dim3(NCHUNK, BH), 256, SMEM_WEDGE>>>(out);
}